// round 17
// baseline (speedup 1.0000x reference)
#include <cuda_runtime.h>
#include <cuda_fp16.h>
#include <cstdint>
#include <cstddef>

#define B_TOT 4096
#define NTOK  49
#define DIM   128
#define NH    4
#define HD    32
#define NW    64
#define SCALE 0.17677669529663687f   // 32^-0.5

// ---------------- device scratch ----------------
// fp16 weight B-fragments packed in jtile PAIRS:
// per (kt, jtp, lane) -> uint4 {jt_even.b0, jt_even.b1, jt_odd.b0, jt_odd.b1}
// q rows (n < 128) pre-scaled by SCALE.
__device__ uint4 g_wqkv16p[8 * 24 * 32];
__device__ uint4 g_wproj16p[8 * 8 * 32];
__device__ float g_qkvb[384];          // qkv bias, q part pre-scaled
// bias+mask, padded: [NW][NH][64 rows][56 cols]; cols>=49 = -1e30, rows>=49 = 0
#define BM_R 64
#define BM_C 56
__device__ float g_bm[NW * NH * BM_R * BM_C];

// ---------------- helpers ----------------
__device__ __forceinline__ uint32_t pack_h2(float a, float b) {
    __half2 h = __floats2half2_rn(a, b);
    return *reinterpret_cast<uint32_t*>(&h);
}

__device__ __forceinline__ void mma_f16(float c[4],
                                        uint32_t a0, uint32_t a1, uint32_t a2, uint32_t a3,
                                        uint32_t b0, uint32_t b1) {
    asm volatile(
        "mma.sync.aligned.m16n8k16.row.col.f32.f16.f16.f32 "
        "{%0,%1,%2,%3}, {%4,%5,%6,%7}, {%8,%9}, {%0,%1,%2,%3};\n"
        : "+f"(c[0]), "+f"(c[1]), "+f"(c[2]), "+f"(c[3])
        : "r"(a0), "r"(a1), "r"(a2), "r"(a3), "r"(b0), "r"(b1));
}

// ---------------- merged prep kernel (one launch) ----------------
__global__ void pack_all_kernel(const float* __restrict__ qkv_w,
                                const float* __restrict__ proj_w,
                                const float* __restrict__ qkv_b,
                                const float* __restrict__ mask,
                                const float* __restrict__ rpb,
                                const int*   __restrict__ rel_index) {
    int idx = blockIdx.x * blockDim.x + threadIdx.x;

    if (idx < 8 * 24 * 32) {
        int kt   = idx / (24 * 32);
        int jtp  = (idx / 32) % 24;
        int lane = idx % 32;
        int ne   = (2 * jtp) * 8 + (lane >> 2);   // even jtile row
        int no   = ne + 8;                        // odd jtile row (same tensor)
        int k0   = kt * 16 + (lane & 3) * 2;
        float s  = (ne < 128) ? SCALE : 1.f;      // fold softmax scale into q
        uint4 v;
        v.x = pack_h2(qkv_w[ne * DIM + k0] * s,     qkv_w[ne * DIM + k0 + 1] * s);
        v.y = pack_h2(qkv_w[ne * DIM + k0 + 8] * s, qkv_w[ne * DIM + k0 + 9] * s);
        v.z = pack_h2(qkv_w[no * DIM + k0] * s,     qkv_w[no * DIM + k0 + 1] * s);
        v.w = pack_h2(qkv_w[no * DIM + k0 + 8] * s, qkv_w[no * DIM + k0 + 9] * s);
        g_wqkv16p[idx] = v;
    }
    if (idx < 8 * 8 * 32) {
        int kt   = idx / (8 * 32);
        int jtp  = (idx / 32) % 8;
        int lane = idx % 32;
        int ne   = (2 * jtp) * 8 + (lane >> 2);
        int no   = ne + 8;
        int k0   = kt * 16 + (lane & 3) * 2;
        uint4 v;
        v.x = pack_h2(proj_w[ne * DIM + k0],     proj_w[ne * DIM + k0 + 1]);
        v.y = pack_h2(proj_w[ne * DIM + k0 + 8], proj_w[ne * DIM + k0 + 9]);
        v.z = pack_h2(proj_w[no * DIM + k0],     proj_w[no * DIM + k0 + 1]);
        v.w = pack_h2(proj_w[no * DIM + k0 + 8], proj_w[no * DIM + k0 + 9]);
        g_wproj16p[idx] = v;
    }
    if (idx < 384) {
        g_qkvb[idx] = qkv_b[idx] * ((idx < 128) ? SCALE : 1.f);
    }

    const int total_bm = NW * NH * BM_R * BM_C;
    if (idx < total_bm) {
        int col = idx % BM_C;
        int row = (idx / BM_C) % BM_R;
        int h   = (idx / (BM_C * BM_R)) % NH;
        int w   = idx / (BM_C * BM_R * NH);
        float v;
        if (row < NTOK && col < NTOK) {
            int r = row * NTOK + col;
            v = rpb[rel_index[r] * NH + h] + mask[w * NTOK * NTOK + r];
        } else if (row < NTOK) {
            v = -1e30f;        // pad column: exp -> 0
        } else {
            v = 0.f;           // pad row: discarded later
        }
        g_bm[idx] = v;
    }
}

// ---------------- smem layout (uint32 units) — TWO windows per CTA ----------
// XF @0      : 8192  x / attnout for 2 windows, A-frag-linear fp16 [128x128]
//              frag index: ((kt*8 + mt)*32 + ln)*4 + reg, mt = 0..7 (win*4+mtw)
// KF @8192   : 8192  k: [win][head][64 tok x 32 dim] B-frag (win*4096 + h*1024)
// VF @16384  : 8192  v: [win][head][k=64 tok x n=32 dim] B-frag
#define XF 0
#define KF 8192
#define VF 16384
#define SMEM_U32 24576    // 98304 bytes; x2 CTAs = 192 KB/SM

extern __shared__ uint32_t smem_u32[];

// GEMM1 tile compute: 4 m-tiles (both windows x 2 local) x 4 jtiles.
// B-fragment held in registers across BOTH windows' A-tiles (the point).
__device__ __forceinline__ void gemm1_tiles4(const uint32_t* sm, int lane,
                                             int mhalf, int jtp0,
                                             float acc[4][4][4]) {
    #pragma unroll
    for (int mi = 0; mi < 4; mi++)
        #pragma unroll
        for (int j = 0; j < 4; j++)
            #pragma unroll
            for (int r = 0; r < 4; r++) acc[mi][j][r] = 0.f;

    #pragma unroll
    for (int kt = 0; kt < 8; ++kt) {
        uint4 af[4];
        #pragma unroll
        for (int mi = 0; mi < 4; mi++) {
            int mt = ((mi >> 1) << 2) + 2 * mhalf + (mi & 1);   // win*4 + mtw
            af[mi] = *(const uint4*)(sm + XF + ((kt * 8 + mt) * 32 + lane) * 4);
        }
        #pragma unroll
        for (int jp = 0; jp < 2; ++jp) {
            uint4 bw = __ldg(&g_wqkv16p[(kt * 24 + jtp0 + jp) * 32 + lane]);
            #pragma unroll
            for (int mi = 0; mi < 4; mi++) {
                mma_f16(acc[mi][2 * jp],     af[mi].x, af[mi].y, af[mi].z, af[mi].w, bw.x, bw.y);
                mma_f16(acc[mi][2 * jp + 1], af[mi].x, af[mi].y, af[mi].z, af[mi].w, bw.z, bw.w);
            }
        }
    }
}

__global__ void __launch_bounds__(256, 2)
win_attn_kernel(const float* __restrict__ x,
                const float* __restrict__ proj_b,
                float* __restrict__ out) {
    const int bp   = blockIdx.x;     // window PAIR: windows 2bp, 2bp+1
    const int tid  = threadIdx.x;
    const int warp = tid >> 5;       // 0..7
    const int lane = tid & 31;
    const int g    = lane >> 2;
    const int tg   = lane & 3;
    const int jq    = warp >> 1;     // 0..3: jtile quad / head id
    const int mhalf = warp & 1;      // 0..1: which pair of m-tiles per window

    uint32_t* sm  = smem_u32;
    char*     smb = reinterpret_cast<char*>(smem_u32);

    // load both windows' x into A-frag-linear fp16; pad rows written as zero
    #pragma unroll
    for (int i = tid; i < 128 * 64; i += 256) {
        int R  = i >> 6;             // global row 0..127 (win*64 + r)
        int c2 = i & 63;
        int c  = c2 * 2;
        int win = R >> 6;
        int r   = R & 63;
        uint32_t val = 0u;
        if (r < NTOK) {
            const float* xb = x + (size_t)(2 * bp + win) * (NTOK * DIM);
            float2 v = *(const float2*)(xb + r * DIM + c);
            val = pack_h2(v.x, v.y);
        }
        int kt  = c >> 4;
        int mt  = R >> 4;
        int ln  = (R & 7) * 4 + (c2 & 3);
        int reg = ((R >> 3) & 1) | (((c >> 3) & 1) << 1);
        sm[XF + ((kt * 8 + mt) * 32 + ln) * 4 + reg] = val;
    }
    __syncthreads();

    // q A-fragments in registers for BOTH windows: qh[win][m][chunk][a0..a3]
    uint32_t qh[2][2][2][4];

    // ---------- GEMM1: 3 passes x (4m x 4j)/warp; order k, v, then q ---------
    // pass k
    {
        float acc[4][4][4];
        gemm1_tiles4(sm, lane, mhalf, 8 + jq * 2, acc);
        #pragma unroll
        for (int j = 0; j < 4; j++) {
            int j2    = (jq * 4 + j) * 8;    // head-space col 0..127
            int jg    = 128 + j2;            // global col
            int h     = j2 >> 5;
            int cl    = (j2 & 31) + tg * 2;
            float2 bb = *(const float2*)(g_qkvb + jg + tg * 2);
            int ktk   = cl >> 4;
            int reg   = (cl >> 3) & 1;
            #pragma unroll
            for (int mi = 0; mi < 4; mi++) {
                int win = mi >> 1;
                int mtw = 2 * mhalf + (mi & 1);
                uint32_t kb = KF + win * 4096 + h * 1024;
                sm[kb + ((ktk * 8 + 2 * mtw) * 32 + lane) * 2 + reg] =
                    pack_h2(acc[mi][j][0] + bb.x, acc[mi][j][1] + bb.y);
                sm[kb + ((ktk * 8 + 2 * mtw + 1) * 32 + lane) * 2 + reg] =
                    pack_h2(acc[mi][j][2] + bb.x, acc[mi][j][3] + bb.y);
            }
        }
    }
    // pass v
    {
        float acc[4][4][4];
        gemm1_tiles4(sm, lane, mhalf, 16 + jq * 2, acc);
        #pragma unroll
        for (int j = 0; j < 4; j++) {
            int j2    = (jq * 4 + j) * 8;    // head-space col 0..127
            int jg    = 256 + j2;
            int h     = j2 >> 5;
            int cl    = (j2 & 31) + tg * 2;
            float2 bb = *(const float2*)(g_qkvb + jg + tg * 2);
            #pragma unroll
            for (int mi = 0; mi < 4; mi++) {
                int win = mi >> 1;
                int mtw = 2 * mhalf + (mi & 1);
                #pragma unroll
                for (int rs = 0; rs < 2; rs++) {
                    int t = mtw * 16 + g + 8 * rs;
                    #pragma unroll
                    for (int cs = 0; cs < 2; cs++) {
                        int   d   = cl + cs;
                        float val = acc[mi][j][rs * 2 + cs] + (cs ? bb.y : bb.x);
                        int ktv = t >> 4;
                        int nt  = d >> 3;
                        int ln  = (d & 7) * 4 + ((t & 7) >> 1);
                        int reg = (t >> 3) & 1;
                        uint32_t slot = VF + win * 4096 + h * 1024 +
                                        ((ktv * 4 + nt) * 32 + ln) * 2 + reg;
                        *reinterpret_cast<__half*>(smb + slot * 4 + (t & 1) * 2) =
                            __float2half_rn(val);
                    }
                }
            }
        }
    }
    // pass q -> registers only (this warp is also the consumer: h = jq)
    {
        float acc[4][4][4];
        gemm1_tiles4(sm, lane, mhalf, jq * 2, acc);
        #pragma unroll
        for (int j = 0; j < 4; j++) {
            int jbase = (jq * 4 + j) * 8;    // 0..127 == h*32 + local dim
            float2 bb = *(const float2*)(g_qkvb + jbase + tg * 2);
            int c = j >> 1;      // 16-dim chunk
            int o = j & 1;       // low/high 8 cols within chunk
            #pragma unroll
            for (int mi = 0; mi < 4; mi++) {
                int win = mi >> 1, m = mi & 1;
                qh[win][m][c][2 * o]     = pack_h2(acc[mi][j][0] + bb.x, acc[mi][j][1] + bb.y);
                qh[win][m][c][2 * o + 1] = pack_h2(acc[mi][j][2] + bb.x, acc[mi][j][3] + bb.y);
            }
        }
    }
    __syncthreads();

    // ---------- fused S -> softmax -> PV; h = jq, both windows ---------------
    const int h = jq;
    #pragma unroll 1
    for (int win = 0; win < 2; ++win) {
        // S for both m units, K fragment loaded ONCE per (c, jt)
        float accS[2][7][4];
        #pragma unroll
        for (int m = 0; m < 2; m++)
            #pragma unroll
            for (int jt = 0; jt < 7; jt++)
                #pragma unroll
                for (int r = 0; r < 4; r++) accS[m][jt][r] = 0.f;

        #pragma unroll
        for (int c = 0; c < 2; ++c) {
            #pragma unroll
            for (int jt = 0; jt < 7; ++jt) {
                uint2 bw = *(const uint2*)(sm + KF + win * 4096 + h * 1024 +
                                           ((c * 8 + jt) * 32 + lane) * 2);
                #pragma unroll
                for (int m = 0; m < 2; m++)
                    mma_f16(accS[m][jt], qh[win][m][c][0], qh[win][m][c][1],
                            qh[win][m][c][2], qh[win][m][c][3], bw.x, bw.y);
            }
        }

        const float* bmw = g_bm + ((size_t)((2 * bp + win) & (NW - 1)) * NH + h) * (BM_R * BM_C);
        uint32_t ph[2][7][2];
        #pragma unroll
        for (int m = 0; m < 2; ++m) {
            const int r0 = (2 * mhalf + m) * 16 + g;
            #pragma unroll
            for (int jt = 0; jt < 7; ++jt) {
                int c0 = jt * 8 + tg * 2;
                float2 bv0 = __ldg((const float2*)(bmw + r0 * BM_C + c0));
                float2 bv1 = __ldg((const float2*)(bmw + (r0 + 8) * BM_C + c0));
                accS[m][jt][0] += bv0.x; accS[m][jt][1] += bv0.y;
                accS[m][jt][2] += bv1.x; accS[m][jt][3] += bv1.y;
            }
            float mx0 = -1e30f, mx1 = -1e30f;
            #pragma unroll
            for (int jt = 0; jt < 7; ++jt) {
                mx0 = fmaxf(mx0, fmaxf(accS[m][jt][0], accS[m][jt][1]));
                mx1 = fmaxf(mx1, fmaxf(accS[m][jt][2], accS[m][jt][3]));
            }
            #pragma unroll
            for (int o = 1; o <= 2; o <<= 1) {
                mx0 = fmaxf(mx0, __shfl_xor_sync(0xffffffffu, mx0, o));
                mx1 = fmaxf(mx1, __shfl_xor_sync(0xffffffffu, mx1, o));
            }
            float s0 = 0.f, s1 = 0.f;
            #pragma unroll
            for (int jt = 0; jt < 7; ++jt) {
                accS[m][jt][0] = __expf(accS[m][jt][0] - mx0); s0 += accS[m][jt][0];
                accS[m][jt][1] = __expf(accS[m][jt][1] - mx0); s0 += accS[m][jt][1];
                accS[m][jt][2] = __expf(accS[m][jt][2] - mx1); s1 += accS[m][jt][2];
                accS[m][jt][3] = __expf(accS[m][jt][3] - mx1); s1 += accS[m][jt][3];
            }
            #pragma unroll
            for (int o = 1; o <= 2; o <<= 1) {
                s0 += __shfl_xor_sync(0xffffffffu, s0, o);
                s1 += __shfl_xor_sync(0xffffffffu, s1, o);
            }
            float i0 = 1.f / s0, i1 = 1.f / s1;
            #pragma unroll
            for (int jt = 0; jt < 7; ++jt) {
                ph[m][jt][0] = pack_h2(accS[m][jt][0] * i0, accS[m][jt][1] * i0);
                ph[m][jt][1] = pack_h2(accS[m][jt][2] * i1, accS[m][jt][3] * i1);
            }
        }

        // PV for both m units, V fragment loaded ONCE per (kt, n)
        float po[2][4][4];
        #pragma unroll
        for (int m = 0; m < 2; m++)
            #pragma unroll
            for (int n = 0; n < 4; n++)
                #pragma unroll
                for (int r = 0; r < 4; r++) po[m][n][r] = 0.f;

        #pragma unroll
        for (int kt = 0; kt < 4; ++kt) {
            #pragma unroll
            for (int n = 0; n < 4; ++n) {
                uint2 bw = *(const uint2*)(sm + VF + win * 4096 + h * 1024 +
                                           ((kt * 4 + n) * 32 + lane) * 2);
                #pragma unroll
                for (int m = 0; m < 2; m++) {
                    uint32_t a0 = ph[m][2 * kt][0], a1 = ph[m][2 * kt][1];
                    uint32_t a2 = (kt < 3) ? ph[m][2 * kt + 1][0] : 0u;
                    uint32_t a3 = (kt < 3) ? ph[m][2 * kt + 1][1] : 0u;
                    mma_f16(po[m][n], a0, a1, a2, a3, bw.x, bw.y);
                }
            }
        }

        // scatter into A-frag-linear attnout (reuses XF)
        #pragma unroll
        for (int m = 0; m < 2; ++m) {
            int mt_g = win * 4 + 2 * mhalf + m;
            #pragma unroll
            for (int n = 0; n < 4; ++n) {
                int cg   = h * 32 + n * 8 + tg * 2;
                int ktx  = cg >> 4;
                int regc = (cg >> 3) & 1;
                uint32_t base = XF + ((ktx * 8 + mt_g) * 32 + lane) * 4;
                sm[base + (regc << 1)]     = pack_h2(po[m][n][0], po[m][n][1]);
                sm[base + 1 + (regc << 1)] = pack_h2(po[m][n][2], po[m][n][3]);
            }
        }
    }
    __syncthreads();

    // ---------- GEMM3: out = attnout @ proj_w^T + proj_b, (4m x 4j)/warp -----
    {
        float acc[4][4][4];
        #pragma unroll
        for (int mi = 0; mi < 4; mi++)
            #pragma unroll
            for (int j = 0; j < 4; j++)
                #pragma unroll
                for (int r = 0; r < 4; r++) acc[mi][j][r] = 0.f;

        #pragma unroll
        for (int kt = 0; kt < 8; ++kt) {
            uint4 af[4];
            #pragma unroll
            for (int mi = 0; mi < 4; mi++) {
                int mt = ((mi >> 1) << 2) + 2 * mhalf + (mi & 1);
                af[mi] = *(const uint4*)(sm + XF + ((kt * 8 + mt) * 32 + lane) * 4);
            }
            #pragma unroll
            for (int jp = 0; jp < 2; ++jp) {
                uint4 bw = __ldg(&g_wproj16p[(kt * 8 + jq * 2 + jp) * 32 + lane]);
                #pragma unroll
                for (int mi = 0; mi < 4; mi++) {
                    mma_f16(acc[mi][2 * jp],     af[mi].x, af[mi].y, af[mi].z, af[mi].w, bw.x, bw.y);
                    mma_f16(acc[mi][2 * jp + 1], af[mi].x, af[mi].y, af[mi].z, af[mi].w, bw.z, bw.w);
                }
            }
        }

        #pragma unroll
        for (int j = 0; j < 4; j++) {
            int jt = jq * 4 + j;
            int c0 = jt * 8 + tg * 2;
            float pb0 = __ldg(proj_b + c0);
            float pb1 = __ldg(proj_b + c0 + 1);
            #pragma unroll
            for (int mi = 0; mi < 4; mi++) {
                int win = mi >> 1;
                int mtw = 2 * mhalf + (mi & 1);
                float* ob = out + (size_t)(2 * bp + win) * (NTOK * DIM);
                int row = mtw * 16 + g;
                if (row < NTOK) {
                    float2 v; v.x = acc[mi][j][0] + pb0; v.y = acc[mi][j][1] + pb1;
                    *(float2*)(ob + row * DIM + c0) = v;
                }
                if (row + 8 < NTOK) {
                    float2 v; v.x = acc[mi][j][2] + pb0; v.y = acc[mi][j][3] + pb1;
                    *(float2*)(ob + (row + 8) * DIM + c0) = v;
                }
            }
        }
    }
}

// ---------------- launch ----------------
extern "C" void kernel_launch(void* const* d_in, const int* in_sizes, int n_in,
                              void* d_out, int out_size) {
    const float* x       = (const float*)d_in[0];
    const float* mask    = (const float*)d_in[1];
    const float* qkv_w   = (const float*)d_in[2];
    const float* qkv_b   = (const float*)d_in[3];
    const float* rpb     = (const float*)d_in[4];
    const float* proj_w  = (const float*)d_in[5];
    const float* proj_b  = (const float*)d_in[6];
    const int*   rel_idx = (const int*)d_in[7];
    float* out = (float*)d_out;

    const int total_bm = NW * NH * BM_R * BM_C;
    pack_all_kernel<<<(total_bm + 255) / 256, 256>>>(qkv_w, proj_w, qkv_b,
                                                     mask, rpb, rel_idx);

    cudaFuncSetAttribute(win_attn_kernel,
                         cudaFuncAttributeMaxDynamicSharedMemorySize,
                         SMEM_U32 * sizeof(uint32_t));
    win_attn_kernel<<<B_TOT / 2, 256, SMEM_U32 * sizeof(uint32_t)>>>(x, proj_b, out);
}